// round 7
// baseline (speedup 1.0000x reference)
#include <cuda_runtime.h>
#include <cuda_fp16.h>
#include <cstdint>

#define S_   1024
#define B_   2
#define D_   1024
#define H_   16
#define DH_  64
#define L_   4
#define WIN_ 64
#define M_   (S_*B_)   // 2048 token rows

// ---------------- scratch (no allocations allowed) ----------------
__device__ float  g_mod[L_*B_*6*D_];
__device__ __half g_xm [M_*D_];        // LN-modulated activations (fp16)
__device__ float  g_qkv[M_*3*D_];      // qkv projections (fp32 for attention)
__device__ __half g_o  [M_*D_];        // attention output (fp16)
__device__ __half g_h  [M_*4*D_];      // MLP hidden (fp16)
// fp16 weight copies
__device__ __half g_wqkv [L_*3*D_*D_];
__device__ __half g_wout [L_*D_*D_];
__device__ __half g_wmlp1[L_*4*D_*D_];
__device__ __half g_wmlp2[L_*D_*4*D_];

__device__ __forceinline__ uint32_t smem_u32(const void* p) {
    uint32_t a; asm("{ .reg .u64 t; cvta.to.shared.u64 t, %1; cvt.u32.u64 %0, t; }" : "=r"(a) : "l"(p));
    return a;
}
__device__ __forceinline__ uint32_t h2u(__half2 h) {
    return *reinterpret_cast<uint32_t*>(&h);
}
#define CP_ASYNC16(dst, src) \
    asm volatile("cp.async.cg.shared.global [%0], [%1], 16;" :: "r"(dst), "l"(src))
#define LDSM4(r0, r1, r2, r3, addr) \
    asm volatile("ldmatrix.sync.aligned.m8n8.x4.shared.b16 {%0,%1,%2,%3}, [%4];" \
        : "=r"(r0), "=r"(r1), "=r"(r2), "=r"(r3) : "r"(addr))

// ---------------- weight convert fp32 -> fp16 ----------------
__global__ void cvt_kernel(const float* __restrict__ src, __half* __restrict__ dst, int n8) {
    int i = blockIdx.x * blockDim.x + threadIdx.x;
    if (i < n8) {
        float4 v0 = reinterpret_cast<const float4*>(src)[2*i];
        float4 v1 = reinterpret_cast<const float4*>(src)[2*i+1];
        uint4 u;
        u.x = h2u(__floats2half2_rn(v0.x, v0.y));
        u.y = h2u(__floats2half2_rn(v0.z, v0.w));
        u.z = h2u(__floats2half2_rn(v1.x, v1.y));
        u.w = h2u(__floats2half2_rn(v1.z, v1.w));
        reinterpret_cast<uint4*>(dst)[i] = u;
    }
}

// ---------------- adaLN modulation ----------------
__global__ void mod_kernel(const float* __restrict__ c,
                           const float* __restrict__ wada,
                           const float* __restrict__ bada) {
    int tid = threadIdx.x, lane = tid & 31;
    int widx = blockIdx.x * 8 + (tid >> 5);
    int l = widx / (6 * D_), j = widx % (6 * D_);
    const float* wr = wada + ((size_t)l * 6 * D_ + j) * D_;
    float a0 = 0.f, a1 = 0.f;
    for (int k = lane; k < D_; k += 32) {
        float wv = wr[k];
        a0 += wv * fmaxf(c[k], 0.f);
        a1 += wv * fmaxf(c[D_ + k], 0.f);
    }
    #pragma unroll
    for (int off = 16; off; off >>= 1) {
        a0 += __shfl_xor_sync(0xffffffffu, a0, off);
        a1 += __shfl_xor_sync(0xffffffffu, a1, off);
    }
    if (lane == 0) {
        float b = bada[l * 6 * D_ + j];
        g_mod[((size_t)l * B_ + 0) * 6 * D_ + j] = a0 + b;
        g_mod[((size_t)l * B_ + 1) * 6 * D_ + j] = a1 + b;
    }
}

// ---------------- LayerNorm + adaLN modulate -> fp16 ----------------
__global__ void ln_mod_kernel(const float* __restrict__ x,
                              const float* __restrict__ mod,
                              int shOff, int scOff,
                              __half* __restrict__ out) {
    int m = blockIdx.x, tid = threadIdx.x;
    const float4* row = reinterpret_cast<const float4*>(x + (size_t)m * D_);
    float4 v = row[tid];
    float s  = v.x + v.y + v.z + v.w;
    float sq = v.x*v.x + v.y*v.y + v.z*v.z + v.w*v.w;
    __shared__ float rs[8], rq[8];
    #pragma unroll
    for (int off = 16; off; off >>= 1) {
        s  += __shfl_xor_sync(0xffffffffu, s,  off);
        sq += __shfl_xor_sync(0xffffffffu, sq, off);
    }
    int lane = tid & 31, wid = tid >> 5;
    if (lane == 0) { rs[wid] = s; rq[wid] = sq; }
    __syncthreads();
    float ts = 0.f, tq = 0.f;
    #pragma unroll
    for (int i = 0; i < 8; i++) { ts += rs[i]; tq += rq[i]; }
    float mean = ts * (1.f / D_);
    float var  = tq * (1.f / D_) - mean * mean;
    float rstd = rsqrtf(var + 1e-6f);
    int b = m & 1;
    const float4* scp = reinterpret_cast<const float4*>(mod + (size_t)b * 6 * D_ + scOff);
    const float4* shp = reinterpret_cast<const float4*>(mod + (size_t)b * 6 * D_ + shOff);
    float4 sc = scp[tid], sh = shp[tid];
    __half2 h0 = __floats2half2_rn((v.x - mean) * rstd * (1.f + sc.x) + sh.x,
                                   (v.y - mean) * rstd * (1.f + sc.y) + sh.y);
    __half2 h1 = __floats2half2_rn((v.z - mean) * rstd * (1.f + sc.z) + sh.z,
                                   (v.w - mean) * rstd * (1.f + sc.w) + sh.w);
    __half2* op = reinterpret_cast<__half2*>(out + (size_t)m * D_);
    op[tid * 2]     = h0;
    op[tid * 2 + 1] = h1;
}

// ---------------- fp16 GEMM: C[M,N] = A[M,K] @ W[N,K]^T (+ epilogue) ----------------
// CTA tile 128 x TN, K-stage 64, 3-stage cp.async. 8 warps: 2(M) x 4(N).
// mode 0: Cf = acc + bias                      (fp32 out)
// mode 1: Ch = half(relu(acc + bias))          (fp16 out)
// mode 2: Cf = xin + gate * (acc + bias)       (fp32 out, gated residual)
#define GP 72          // smem row pitch in halves (144 B)
template<int TN>
__global__ __launch_bounds__(256, 2)
void gemm_fp16(const __half* __restrict__ A, const __half* __restrict__ W,
               const float* __restrict__ bias,
               float* __restrict__ Cf, __half* __restrict__ Ch,
               const float* __restrict__ xin, const float* __restrict__ mod, int gateOff,
               int N, int K, int mode)
{
    constexpr int NT = TN / 32;                 // n8 frags per warp (4 or 2)
    constexpr int ABYTES = 128 * GP * 2;        // 18432
    constexpr int BBYTES = TN * GP * 2;
    constexpr int STG = ABYTES + BBYTES;
    extern __shared__ char smraw[];
    uint32_t sbase = smem_u32(smraw);
    int tid = threadIdx.x, lane = tid & 31, w = tid >> 5;
    int warpM = w >> 2, warpN = w & 3;          // 2 x 4
    int g = lane >> 2, q = lane & 3;
    int bm = blockIdx.y * 128, bn = blockIdx.x * TN;

    uint32_t aoff2 = 2u * (((lane & 7) + (lane & 8)) * GP + ((lane & 16) >> 1));
    uint32_t boff2 = 2u * (((lane & 7) + ((lane & 16) >> 1)) * GP + (lane & 8));

    auto loadStage = [&](int slot, int kidx) {
        int k0 = kidx << 6;
        uint32_t aB = sbase + slot * STG;
        #pragma unroll
        for (int i = 0; i < 4; i++) {
            int seg = tid + i * 256;
            int row = seg >> 3, c = seg & 7;
            CP_ASYNC16(aB + row * (GP*2) + c * 16,
                       A + (size_t)(bm + row) * K + k0 + c * 8);
        }
        #pragma unroll
        for (int i = 0; i < TN / 32; i++) {
            int seg = tid + i * 256;
            int row = seg >> 3, c = seg & 7;
            CP_ASYNC16(aB + ABYTES + row * (GP*2) + c * 16,
                       W + (size_t)(bn + row) * K + k0 + c * 8);
        }
        asm volatile("cp.async.commit_group;");
    };

    float acc[4][NT][4];
    #pragma unroll
    for (int i = 0; i < 4; i++)
        #pragma unroll
        for (int j = 0; j < NT; j++)
            #pragma unroll
            for (int k = 0; k < 4; k++) acc[i][j][k] = 0.f;

    const int T = K >> 6;
    loadStage(0, 0);
    loadStage(1, 1);

    for (int t = 0; t < T; t++) {
        if (t < T - 1) asm volatile("cp.async.wait_group 1;");
        else           asm volatile("cp.async.wait_group 0;");
        __syncthreads();
        if (t + 2 < T) loadStage((t + 2) % 3, t + 2);

        uint32_t aBase = sbase + (t % 3) * STG;
        uint32_t bBase = aBase + ABYTES;
        #pragma unroll
        for (int kk = 0; kk < 4; kk++) {
            uint32_t af[4][4];
            #pragma unroll
            for (int mt = 0; mt < 4; mt++) {
                uint32_t ad = aBase + 2u * ((warpM * 64 + mt * 16) * GP + kk * 16) + aoff2;
                LDSM4(af[mt][0], af[mt][1], af[mt][2], af[mt][3], ad);
            }
            uint32_t bf[NT][2];
            #pragma unroll
            for (int nb = 0; nb < NT / 2; nb++) {
                uint32_t bd = bBase + 2u * ((warpN * (TN/4) + nb * 16) * GP + kk * 16) + boff2;
                uint32_t r0, r1, r2, r3;
                LDSM4(r0, r1, r2, r3, bd);
                bf[2*nb][0] = r0;   bf[2*nb][1] = r1;
                bf[2*nb+1][0] = r2; bf[2*nb+1][1] = r3;
            }
            #pragma unroll
            for (int mt = 0; mt < 4; mt++)
                #pragma unroll
                for (int nt = 0; nt < NT; nt++)
                    asm volatile(
                        "mma.sync.aligned.m16n8k16.row.col.f32.f16.f16.f32 "
                        "{%0,%1,%2,%3}, {%4,%5,%6,%7}, {%8,%9}, {%0,%1,%2,%3};"
                        : "+f"(acc[mt][nt][0]), "+f"(acc[mt][nt][1]),
                          "+f"(acc[mt][nt][2]), "+f"(acc[mt][nt][3])
                        : "r"(af[mt][0]), "r"(af[mt][1]), "r"(af[mt][2]), "r"(af[mt][3]),
                          "r"(bf[nt][0]), "r"(bf[nt][1]));
        }
    }

    // epilogue
    float bz[NT][2], gz[2][NT][2];
    #pragma unroll
    for (int nt = 0; nt < NT; nt++) {
        int col = bn + warpN * (TN/4) + nt * 8 + q * 2;
        bz[nt][0] = bias[col];
        bz[nt][1] = bias[col + 1];
        if (mode == 2) {
            gz[0][nt][0] = mod[gateOff + col];
            gz[0][nt][1] = mod[gateOff + col + 1];
            gz[1][nt][0] = mod[6 * D_ + gateOff + col];
            gz[1][nt][1] = mod[6 * D_ + gateOff + col + 1];
        }
    }
    #pragma unroll
    for (int mt = 0; mt < 4; mt++) {
        #pragma unroll
        for (int half = 0; half < 2; half++) {
            int r = warpM * 64 + mt * 16 + g + half * 8;
            size_t rowoff = (size_t)(bm + r) * N;
            int par = r & 1;
            #pragma unroll
            for (int nt = 0; nt < NT; nt++) {
                int col = bn + warpN * (TN/4) + nt * 8 + q * 2;
                float v0 = acc[mt][nt][half * 2 + 0] + bz[nt][0];
                float v1 = acc[mt][nt][half * 2 + 1] + bz[nt][1];
                if (mode == 1) {
                    __half2 hv = __floats2half2_rn(fmaxf(v0, 0.f), fmaxf(v1, 0.f));
                    *reinterpret_cast<__half2*>(Ch + rowoff + col) = hv;
                } else if (mode == 2) {
                    float2 xi = *reinterpret_cast<const float2*>(xin + rowoff + col);
                    float2 r2;
                    r2.x = xi.x + gz[par][nt][0] * v0;
                    r2.y = xi.y + gz[par][nt][1] * v1;
                    *reinterpret_cast<float2*>(Cf + rowoff + col) = r2;
                } else {
                    float2 r2; r2.x = v0; r2.y = v1;
                    *reinterpret_cast<float2*>(Cf + rowoff + col) = r2;
                }
            }
        }
    }
}

// ---------------- windowed attention (flash-style, 4-key groups) ----------------
__global__ __launch_bounds__(512) void attn_kernel(const float* __restrict__ qkv,
                                                   __half* __restrict__ o) {
    __shared__ float Ks[32][64];
    __shared__ float Vs[32][64];
    int tid = threadIdx.x, lane = tid & 31, w = tid >> 5;
    int bh = blockIdx.y;
    int b = bh / H_, h = bh % H_;
    int s0 = blockIdx.x * 16;
    int s  = s0 + w;

    const float* qptr = qkv + ((size_t)(s * B_ + b)) * (3 * D_) + h * DH_;
    float q0 = qptr[lane], q1 = qptr[lane + 32];

    float mx = 0.f, lsum = 0.f, o0 = 0.f, o1 = 0.f;
    int tlo = s0 - WIN_;       if (tlo < 0) tlo = 0;
    int thi = s0 + 15 + WIN_;  if (thi > S_ - 1) thi = S_ - 1;
    int jload = tid >> 6, dload = tid & 63;

    for (int tb = tlo; tb <= thi; tb += 32) {
        __syncthreads();
        for (int jj = jload; jj < 32; jj += 8) {
            int t = tb + jj; if (t > thi) t = thi;
            const float* kp = qkv + ((size_t)(t * B_ + b)) * (3 * D_) + D_ + h * DH_;
            Ks[jj][dload] = kp[dload];
            Vs[jj][dload] = kp[D_ + dload];
        }
        __syncthreads();
        #pragma unroll
        for (int jj = 0; jj < 32; jj += 4) {
            float sc[4];
            #pragma unroll
            for (int i = 0; i < 4; i++) {
                int t = tb + jj + i;
                float dp = q0 * Ks[jj + i][lane] + q1 * Ks[jj + i][lane + 32];
                #pragma unroll
                for (int off = 16; off; off >>= 1)
                    dp += __shfl_xor_sync(0xffffffffu, dp, off);
                int dist = t - s; if (dist < 0) dist = -dist;
                sc[i] = (dist <= WIN_ && t <= thi) ? dp * 0.125f : -1e30f;
            }
            float mnew = fmaxf(fmaxf(fmaxf(sc[0], sc[1]), fmaxf(sc[2], sc[3])), mx);
            float corr = __expf(mx - mnew);
            float p0 = __expf(sc[0] - mnew);
            float p1 = __expf(sc[1] - mnew);
            float p2 = __expf(sc[2] - mnew);
            float p3 = __expf(sc[3] - mnew);
            lsum = lsum * corr + ((p0 + p1) + (p2 + p3));
            o0 = o0 * corr + p0 * Vs[jj][lane]     + p1 * Vs[jj + 1][lane]
                           + p2 * Vs[jj + 2][lane] + p3 * Vs[jj + 3][lane];
            o1 = o1 * corr + p0 * Vs[jj][lane + 32]     + p1 * Vs[jj + 1][lane + 32]
                           + p2 * Vs[jj + 2][lane + 32] + p3 * Vs[jj + 3][lane + 32];
            mx = mnew;
        }
    }
    float inv = 1.f / lsum;
    __half* op = o + ((size_t)(s * B_ + b)) * D_ + h * DH_;
    op[lane]      = __float2half_rn(o0 * inv);
    op[lane + 32] = __float2half_rn(o1 * inv);
}

// ---------------- launcher ----------------
extern "C" void kernel_launch(void* const* d_in, const int* in_sizes, int n_in,
                              void* d_out, int out_size) {
    const float* x_in   = (const float*)d_in[0];
    const float* c      = (const float*)d_in[1];
    const float* w_qkv  = (const float*)d_in[2];
    const float* b_qkv  = (const float*)d_in[3];
    const float* w_out  = (const float*)d_in[4];
    const float* b_out  = (const float*)d_in[5];
    const float* w_mlp1 = (const float*)d_in[6];
    const float* b_mlp1 = (const float*)d_in[7];
    const float* w_mlp2 = (const float*)d_in[8];
    const float* b_mlp2 = (const float*)d_in[9];
    const float* w_ada  = (const float*)d_in[10];
    const float* b_ada  = (const float*)d_in[11];
    float* x = (float*)d_out;

    float  *mod, *qkv;
    __half *xm, *o, *h, *wq, *wo, *w1, *w2;
    cudaGetSymbolAddress((void**)&mod, g_mod);
    cudaGetSymbolAddress((void**)&xm,  g_xm);
    cudaGetSymbolAddress((void**)&qkv, g_qkv);
    cudaGetSymbolAddress((void**)&o,   g_o);
    cudaGetSymbolAddress((void**)&h,   g_h);
    cudaGetSymbolAddress((void**)&wq,  g_wqkv);
    cudaGetSymbolAddress((void**)&wo,  g_wout);
    cudaGetSymbolAddress((void**)&w1,  g_wmlp1);
    cudaGetSymbolAddress((void**)&w2,  g_wmlp2);

    const int smem128 = 3 * (128 * GP * 2 + 128 * GP * 2);  // 110592
    const int smem64  = 3 * (128 * GP * 2 + 64  * GP * 2);  // 82944
    cudaFuncSetAttribute(gemm_fp16<128>, cudaFuncAttributeMaxDynamicSharedMemorySize, smem128);
    cudaFuncSetAttribute(gemm_fp16<64>,  cudaFuncAttributeMaxDynamicSharedMemorySize, smem64);

    cudaMemcpyAsync(x, x_in, (size_t)M_ * D_ * sizeof(float), cudaMemcpyDeviceToDevice);

    // weight convert fp32 -> fp16
    {
        int n;
        n = L_*3*D_*D_/8;  cvt_kernel<<<(n+255)/256, 256>>>(w_qkv,  wq, n);
        n = L_*D_*D_/8;    cvt_kernel<<<(n+255)/256, 256>>>(w_out,  wo, n);
        n = L_*4*D_*D_/8;  cvt_kernel<<<(n+255)/256, 256>>>(w_mlp1, w1, n);
        n = L_*D_*4*D_/8;  cvt_kernel<<<(n+255)/256, 256>>>(w_mlp2, w2, n);
    }

    mod_kernel<<<(L_ * 6 * D_) / 8, 256>>>(c, w_ada, b_ada);

    for (int l = 0; l < L_; l++) {
        const float* modl = mod + (size_t)l * B_ * 6 * D_;
        // --- attention branch ---
        ln_mod_kernel<<<M_, 256>>>(x, modl, 0, D_, xm);
        gemm_fp16<128><<<dim3(3 * D_ / 128, M_ / 128), 256, smem128>>>(
            xm, wq + (size_t)l * 3 * D_ * D_, b_qkv + (size_t)l * 3 * D_,
            qkv, nullptr, nullptr, nullptr, 0, 3 * D_, D_, 0);
        attn_kernel<<<dim3(S_ / 16, B_ * H_), 512>>>(qkv, o);
        gemm_fp16<64><<<dim3(D_ / 64, M_ / 128), 256, smem64>>>(
            o, wo + (size_t)l * D_ * D_, b_out + (size_t)l * D_,
            x, nullptr, x, modl, 2 * D_, D_, D_, 2);
        // --- MLP branch ---
        ln_mod_kernel<<<M_, 256>>>(x, modl, 3 * D_, 4 * D_, xm);
        gemm_fp16<128><<<dim3(4 * D_ / 128, M_ / 128), 256, smem128>>>(
            xm, w1 + (size_t)l * 4 * D_ * D_, b_mlp1 + (size_t)l * 4 * D_,
            nullptr, h, nullptr, nullptr, 0, 4 * D_, D_, 1);
        gemm_fp16<64><<<dim3(D_ / 64, M_ / 128), 256, smem64>>>(
            h, w2 + (size_t)l * D_ * 4 * D_, b_mlp2 + (size_t)l * D_,
            x, nullptr, x, modl, 5 * D_, D_, 4 * D_, 2);
    }
}

// round 8
// speedup vs baseline: 1.0019x; 1.0019x over previous
#include <cuda_runtime.h>
#include <cuda_fp16.h>
#include <cstdint>

#define S_   1024
#define B_   2
#define D_   1024
#define H_   16
#define DH_  64
#define L_   4
#define WIN_ 64
#define M_   (S_*B_)   // 2048 token rows

// ---------------- scratch (no allocations allowed) ----------------
__device__ float  g_mod[L_*B_*6*D_];
__device__ __half g_xm [M_*D_];        // LN-modulated activations (fp16)
__device__ float  g_qkv[M_*3*D_];      // qkv projections (fp32 for attention)
__device__ __half g_o  [M_*D_];        // attention output (fp16)
__device__ __half g_h  [M_*4*D_];      // MLP hidden (fp16)
// fp16 weight copies
__device__ __half g_wqkv [L_*3*D_*D_];
__device__ __half g_wout [L_*D_*D_];
__device__ __half g_wmlp1[L_*4*D_*D_];
__device__ __half g_wmlp2[L_*D_*4*D_];

__device__ __forceinline__ uint32_t smem_u32(const void* p) {
    uint32_t a; asm("{ .reg .u64 t; cvta.to.shared.u64 t, %1; cvt.u32.u64 %0, t; }" : "=r"(a) : "l"(p));
    return a;
}
__device__ __forceinline__ uint32_t h2u(__half2 h) {
    return *reinterpret_cast<uint32_t*>(&h);
}
#define CP_ASYNC16(dst, src) \
    asm volatile("cp.async.cg.shared.global [%0], [%1], 16;" :: "r"(dst), "l"(src))
#define LDSM4(r0, r1, r2, r3, addr) \
    asm volatile("ldmatrix.sync.aligned.m8n8.x4.shared.b16 {%0,%1,%2,%3}, [%4];" \
        : "=r"(r0), "=r"(r1), "=r"(r2), "=r"(r3) : "r"(addr))

// ---------------- weight convert fp32 -> fp16 ----------------
__global__ void cvt_kernel(const float* __restrict__ src, __half* __restrict__ dst, int n8) {
    int i = blockIdx.x * blockDim.x + threadIdx.x;
    if (i < n8) {
        float4 v0 = reinterpret_cast<const float4*>(src)[2*i];
        float4 v1 = reinterpret_cast<const float4*>(src)[2*i+1];
        uint4 u;
        u.x = h2u(__floats2half2_rn(v0.x, v0.y));
        u.y = h2u(__floats2half2_rn(v0.z, v0.w));
        u.z = h2u(__floats2half2_rn(v1.x, v1.y));
        u.w = h2u(__floats2half2_rn(v1.z, v1.w));
        reinterpret_cast<uint4*>(dst)[i] = u;
    }
}

// ---------------- adaLN modulation ----------------
__global__ void mod_kernel(const float* __restrict__ c,
                           const float* __restrict__ wada,
                           const float* __restrict__ bada) {
    int tid = threadIdx.x, lane = tid & 31;
    int widx = blockIdx.x * 8 + (tid >> 5);
    int l = widx / (6 * D_), j = widx % (6 * D_);
    const float* wr = wada + ((size_t)l * 6 * D_ + j) * D_;
    float a0 = 0.f, a1 = 0.f;
    for (int k = lane; k < D_; k += 32) {
        float wv = wr[k];
        a0 += wv * fmaxf(c[k], 0.f);
        a1 += wv * fmaxf(c[D_ + k], 0.f);
    }
    #pragma unroll
    for (int off = 16; off; off >>= 1) {
        a0 += __shfl_xor_sync(0xffffffffu, a0, off);
        a1 += __shfl_xor_sync(0xffffffffu, a1, off);
    }
    if (lane == 0) {
        float b = bada[l * 6 * D_ + j];
        g_mod[((size_t)l * B_ + 0) * 6 * D_ + j] = a0 + b;
        g_mod[((size_t)l * B_ + 1) * 6 * D_ + j] = a1 + b;
    }
}

// ---------------- LayerNorm + adaLN modulate -> fp16 ----------------
__global__ void ln_mod_kernel(const float* __restrict__ x,
                              const float* __restrict__ mod,
                              int shOff, int scOff,
                              __half* __restrict__ out) {
    int m = blockIdx.x, tid = threadIdx.x;
    const float4* row = reinterpret_cast<const float4*>(x + (size_t)m * D_);
    float4 v = row[tid];
    float s  = v.x + v.y + v.z + v.w;
    float sq = v.x*v.x + v.y*v.y + v.z*v.z + v.w*v.w;
    __shared__ float rs[8], rq[8];
    #pragma unroll
    for (int off = 16; off; off >>= 1) {
        s  += __shfl_xor_sync(0xffffffffu, s,  off);
        sq += __shfl_xor_sync(0xffffffffu, sq, off);
    }
    int lane = tid & 31, wid = tid >> 5;
    if (lane == 0) { rs[wid] = s; rq[wid] = sq; }
    __syncthreads();
    float ts = 0.f, tq = 0.f;
    #pragma unroll
    for (int i = 0; i < 8; i++) { ts += rs[i]; tq += rq[i]; }
    float mean = ts * (1.f / D_);
    float var  = tq * (1.f / D_) - mean * mean;
    float rstd = rsqrtf(var + 1e-6f);
    int b = m & 1;
    const float4* scp = reinterpret_cast<const float4*>(mod + (size_t)b * 6 * D_ + scOff);
    const float4* shp = reinterpret_cast<const float4*>(mod + (size_t)b * 6 * D_ + shOff);
    float4 sc = scp[tid], sh = shp[tid];
    __half2 h0 = __floats2half2_rn((v.x - mean) * rstd * (1.f + sc.x) + sh.x,
                                   (v.y - mean) * rstd * (1.f + sc.y) + sh.y);
    __half2 h1 = __floats2half2_rn((v.z - mean) * rstd * (1.f + sc.z) + sh.z,
                                   (v.w - mean) * rstd * (1.f + sc.w) + sh.w);
    __half2* op = reinterpret_cast<__half2*>(out + (size_t)m * D_);
    op[tid * 2]     = h0;
    op[tid * 2 + 1] = h1;
}

// ---------------- fp16 GEMM: C[M,N] = A[M,K] @ W[N,K]^T (+ epilogue) ----------------
// CTA tile 128 x TN, K-stage 64, 3-stage cp.async. 8 warps: 2(M) x 4(N).
// mode 0: Cf = acc + bias                      (fp32 out)
// mode 1: Ch = half(relu(acc + bias))          (fp16 out)
// mode 2: Cf = xin + gate * (acc + bias)       (fp32 out, gated residual)
#define GP 72          // smem row pitch in halves (144 B)
template<int TN>
__global__ __launch_bounds__(256, 2)
void gemm_fp16(const __half* __restrict__ A, const __half* __restrict__ W,
               const float* __restrict__ bias,
               float* __restrict__ Cf, __half* __restrict__ Ch,
               const float* __restrict__ xin, const float* __restrict__ mod, int gateOff,
               int N, int K, int mode)
{
    constexpr int NT = TN / 32;                 // n8 frags per warp (4 or 2)
    constexpr int ABYTES = 128 * GP * 2;        // 18432
    constexpr int BBYTES = TN * GP * 2;
    constexpr int STG = ABYTES + BBYTES;
    extern __shared__ char smraw[];
    uint32_t sbase = smem_u32(smraw);
    int tid = threadIdx.x, lane = tid & 31, w = tid >> 5;
    int warpM = w >> 2, warpN = w & 3;          // 2 x 4
    int g = lane >> 2, q = lane & 3;
    int bm = blockIdx.y * 128, bn = blockIdx.x * TN;

    uint32_t aoff2 = 2u * (((lane & 7) + (lane & 8)) * GP + ((lane & 16) >> 1));
    uint32_t boff2 = 2u * (((lane & 7) + ((lane & 16) >> 1)) * GP + (lane & 8));

    auto loadStage = [&](int slot, int kidx) {
        int k0 = kidx << 6;
        uint32_t aB = sbase + slot * STG;
        #pragma unroll
        for (int i = 0; i < 4; i++) {
            int seg = tid + i * 256;
            int row = seg >> 3, c = seg & 7;
            CP_ASYNC16(aB + row * (GP*2) + c * 16,
                       A + (size_t)(bm + row) * K + k0 + c * 8);
        }
        #pragma unroll
        for (int i = 0; i < TN / 32; i++) {
            int seg = tid + i * 256;
            int row = seg >> 3, c = seg & 7;
            CP_ASYNC16(aB + ABYTES + row * (GP*2) + c * 16,
                       W + (size_t)(bn + row) * K + k0 + c * 8);
        }
        asm volatile("cp.async.commit_group;");
    };

    float acc[4][NT][4];
    #pragma unroll
    for (int i = 0; i < 4; i++)
        #pragma unroll
        for (int j = 0; j < NT; j++)
            #pragma unroll
            for (int k = 0; k < 4; k++) acc[i][j][k] = 0.f;

    const int T = K >> 6;
    loadStage(0, 0);
    loadStage(1, 1);

    for (int t = 0; t < T; t++) {
        if (t < T - 1) asm volatile("cp.async.wait_group 1;");
        else           asm volatile("cp.async.wait_group 0;");
        __syncthreads();
        if (t + 2 < T) loadStage((t + 2) % 3, t + 2);

        uint32_t aBase = sbase + (t % 3) * STG;
        uint32_t bBase = aBase + ABYTES;
        #pragma unroll
        for (int kk = 0; kk < 4; kk++) {
            uint32_t af[4][4];
            #pragma unroll
            for (int mt = 0; mt < 4; mt++) {
                uint32_t ad = aBase + 2u * ((warpM * 64 + mt * 16) * GP + kk * 16) + aoff2;
                LDSM4(af[mt][0], af[mt][1], af[mt][2], af[mt][3], ad);
            }
            uint32_t bf[NT][2];
            #pragma unroll
            for (int nb = 0; nb < NT / 2; nb++) {
                uint32_t bd = bBase + 2u * ((warpN * (TN/4) + nb * 16) * GP + kk * 16) + boff2;
                uint32_t r0, r1, r2, r3;
                LDSM4(r0, r1, r2, r3, bd);
                bf[2*nb][0] = r0;   bf[2*nb][1] = r1;
                bf[2*nb+1][0] = r2; bf[2*nb+1][1] = r3;
            }
            #pragma unroll
            for (int mt = 0; mt < 4; mt++)
                #pragma unroll
                for (int nt = 0; nt < NT; nt++)
                    asm volatile(
                        "mma.sync.aligned.m16n8k16.row.col.f32.f16.f16.f32 "
                        "{%0,%1,%2,%3}, {%4,%5,%6,%7}, {%8,%9}, {%0,%1,%2,%3};"
                        : "+f"(acc[mt][nt][0]), "+f"(acc[mt][nt][1]),
                          "+f"(acc[mt][nt][2]), "+f"(acc[mt][nt][3])
                        : "r"(af[mt][0]), "r"(af[mt][1]), "r"(af[mt][2]), "r"(af[mt][3]),
                          "r"(bf[nt][0]), "r"(bf[nt][1]));
        }
    }

    // epilogue
    float bz[NT][2], gz[2][NT][2];
    #pragma unroll
    for (int nt = 0; nt < NT; nt++) {
        int col = bn + warpN * (TN/4) + nt * 8 + q * 2;
        bz[nt][0] = bias[col];
        bz[nt][1] = bias[col + 1];
        if (mode == 2) {
            gz[0][nt][0] = mod[gateOff + col];
            gz[0][nt][1] = mod[gateOff + col + 1];
            gz[1][nt][0] = mod[6 * D_ + gateOff + col];
            gz[1][nt][1] = mod[6 * D_ + gateOff + col + 1];
        }
    }
    #pragma unroll
    for (int mt = 0; mt < 4; mt++) {
        #pragma unroll
        for (int half = 0; half < 2; half++) {
            int r = warpM * 64 + mt * 16 + g + half * 8;
            size_t rowoff = (size_t)(bm + r) * N;
            int par = r & 1;
            #pragma unroll
            for (int nt = 0; nt < NT; nt++) {
                int col = bn + warpN * (TN/4) + nt * 8 + q * 2;
                float v0 = acc[mt][nt][half * 2 + 0] + bz[nt][0];
                float v1 = acc[mt][nt][half * 2 + 1] + bz[nt][1];
                if (mode == 1) {
                    __half2 hv = __floats2half2_rn(fmaxf(v0, 0.f), fmaxf(v1, 0.f));
                    *reinterpret_cast<__half2*>(Ch + rowoff + col) = hv;
                } else if (mode == 2) {
                    float2 xi = *reinterpret_cast<const float2*>(xin + rowoff + col);
                    float2 r2;
                    r2.x = xi.x + gz[par][nt][0] * v0;
                    r2.y = xi.y + gz[par][nt][1] * v1;
                    *reinterpret_cast<float2*>(Cf + rowoff + col) = r2;
                } else {
                    float2 r2; r2.x = v0; r2.y = v1;
                    *reinterpret_cast<float2*>(Cf + rowoff + col) = r2;
                }
            }
        }
    }
}

// ---------------- windowed attention (flash-style, 4-key groups) ----------------
__global__ __launch_bounds__(512) void attn_kernel(const float* __restrict__ qkv,
                                                   __half* __restrict__ o) {
    __shared__ float Ks[32][64];
    __shared__ float Vs[32][64];
    int tid = threadIdx.x, lane = tid & 31, w = tid >> 5;
    int bh = blockIdx.y;
    int b = bh / H_, h = bh % H_;
    int s0 = blockIdx.x * 16;
    int s  = s0 + w;

    const float* qptr = qkv + ((size_t)(s * B_ + b)) * (3 * D_) + h * DH_;
    float q0 = qptr[lane], q1 = qptr[lane + 32];

    float mx = 0.f, lsum = 0.f, o0 = 0.f, o1 = 0.f;
    int tlo = s0 - WIN_;       if (tlo < 0) tlo = 0;
    int thi = s0 + 15 + WIN_;  if (thi > S_ - 1) thi = S_ - 1;
    int jload = tid >> 6, dload = tid & 63;

    for (int tb = tlo; tb <= thi; tb += 32) {
        __syncthreads();
        for (int jj = jload; jj < 32; jj += 8) {
            int t = tb + jj; if (t > thi) t = thi;
            const float* kp = qkv + ((size_t)(t * B_ + b)) * (3 * D_) + D_ + h * DH_;
            Ks[jj][dload] = kp[dload];
            Vs[jj][dload] = kp[D_ + dload];
        }
        __syncthreads();
        #pragma unroll
        for (int jj = 0; jj < 32; jj += 4) {
            float sc[4];
            #pragma unroll
            for (int i = 0; i < 4; i++) {
                int t = tb + jj + i;
                float dp = q0 * Ks[jj + i][lane] + q1 * Ks[jj + i][lane + 32];
                #pragma unroll
                for (int off = 16; off; off >>= 1)
                    dp += __shfl_xor_sync(0xffffffffu, dp, off);
                int dist = t - s; if (dist < 0) dist = -dist;
                sc[i] = (dist <= WIN_ && t <= thi) ? dp * 0.125f : -1e30f;
            }
            float mnew = fmaxf(fmaxf(fmaxf(sc[0], sc[1]), fmaxf(sc[2], sc[3])), mx);
            float corr = __expf(mx - mnew);
            float p0 = __expf(sc[0] - mnew);
            float p1 = __expf(sc[1] - mnew);
            float p2 = __expf(sc[2] - mnew);
            float p3 = __expf(sc[3] - mnew);
            lsum = lsum * corr + ((p0 + p1) + (p2 + p3));
            o0 = o0 * corr + p0 * Vs[jj][lane]     + p1 * Vs[jj + 1][lane]
                           + p2 * Vs[jj + 2][lane] + p3 * Vs[jj + 3][lane];
            o1 = o1 * corr + p0 * Vs[jj][lane + 32]     + p1 * Vs[jj + 1][lane + 32]
                           + p2 * Vs[jj + 2][lane + 32] + p3 * Vs[jj + 3][lane + 32];
            mx = mnew;
        }
    }
    float inv = 1.f / lsum;
    __half* op = o + ((size_t)(s * B_ + b)) * D_ + h * DH_;
    op[lane]      = __float2half_rn(o0 * inv);
    op[lane + 32] = __float2half_rn(o1 * inv);
}

// ---------------- launcher ----------------
extern "C" void kernel_launch(void* const* d_in, const int* in_sizes, int n_in,
                              void* d_out, int out_size) {
    const float* x_in   = (const float*)d_in[0];
    const float* c      = (const float*)d_in[1];
    const float* w_qkv  = (const float*)d_in[2];
    const float* b_qkv  = (const float*)d_in[3];
    const float* w_out  = (const float*)d_in[4];
    const float* b_out  = (const float*)d_in[5];
    const float* w_mlp1 = (const float*)d_in[6];
    const float* b_mlp1 = (const float*)d_in[7];
    const float* w_mlp2 = (const float*)d_in[8];
    const float* b_mlp2 = (const float*)d_in[9];
    const float* w_ada  = (const float*)d_in[10];
    const float* b_ada  = (const float*)d_in[11];
    float* x = (float*)d_out;

    float  *mod, *qkv;
    __half *xm, *o, *h, *wq, *wo, *w1, *w2;
    cudaGetSymbolAddress((void**)&mod, g_mod);
    cudaGetSymbolAddress((void**)&xm,  g_xm);
    cudaGetSymbolAddress((void**)&qkv, g_qkv);
    cudaGetSymbolAddress((void**)&o,   g_o);
    cudaGetSymbolAddress((void**)&h,   g_h);
    cudaGetSymbolAddress((void**)&wq,  g_wqkv);
    cudaGetSymbolAddress((void**)&wo,  g_wout);
    cudaGetSymbolAddress((void**)&w1,  g_wmlp1);
    cudaGetSymbolAddress((void**)&w2,  g_wmlp2);

    const int smem128 = 3 * (128 * GP * 2 + 128 * GP * 2);  // 110592
    const int smem64  = 3 * (128 * GP * 2 + 64  * GP * 2);  // 82944
    cudaFuncSetAttribute(gemm_fp16<128>, cudaFuncAttributeMaxDynamicSharedMemorySize, smem128);
    cudaFuncSetAttribute(gemm_fp16<64>,  cudaFuncAttributeMaxDynamicSharedMemorySize, smem64);

    cudaMemcpyAsync(x, x_in, (size_t)M_ * D_ * sizeof(float), cudaMemcpyDeviceToDevice);

    // weight convert fp32 -> fp16
    {
        int n;
        n = L_*3*D_*D_/8;  cvt_kernel<<<(n+255)/256, 256>>>(w_qkv,  wq, n);
        n = L_*D_*D_/8;    cvt_kernel<<<(n+255)/256, 256>>>(w_out,  wo, n);
        n = L_*4*D_*D_/8;  cvt_kernel<<<(n+255)/256, 256>>>(w_mlp1, w1, n);
        n = L_*D_*4*D_/8;  cvt_kernel<<<(n+255)/256, 256>>>(w_mlp2, w2, n);
    }

    mod_kernel<<<(L_ * 6 * D_) / 8, 256>>>(c, w_ada, b_ada);

    for (int l = 0; l < L_; l++) {
        const float* modl = mod + (size_t)l * B_ * 6 * D_;
        // --- attention branch ---
        ln_mod_kernel<<<M_, 256>>>(x, modl, 0, D_, xm);
        gemm_fp16<128><<<dim3(3 * D_ / 128, M_ / 128), 256, smem128>>>(
            xm, wq + (size_t)l * 3 * D_ * D_, b_qkv + (size_t)l * 3 * D_,
            qkv, nullptr, nullptr, nullptr, 0, 3 * D_, D_, 0);
        attn_kernel<<<dim3(S_ / 16, B_ * H_), 512>>>(qkv, o);
        gemm_fp16<64><<<dim3(D_ / 64, M_ / 128), 256, smem64>>>(
            o, wo + (size_t)l * D_ * D_, b_out + (size_t)l * D_,
            x, nullptr, x, modl, 2 * D_, D_, D_, 2);
        // --- MLP branch ---
        ln_mod_kernel<<<M_, 256>>>(x, modl, 3 * D_, 4 * D_, xm);
        gemm_fp16<128><<<dim3(4 * D_ / 128, M_ / 128), 256, smem128>>>(
            xm, w1 + (size_t)l * 4 * D_ * D_, b_mlp1 + (size_t)l * 4 * D_,
            nullptr, h, nullptr, nullptr, 0, 4 * D_, D_, 1);
        gemm_fp16<64><<<dim3(D_ / 64, M_ / 128), 256, smem64>>>(
            h, w2 + (size_t)l * D_ * 4 * D_, b_mlp2 + (size_t)l * D_,
            x, nullptr, x, modl, 5 * D_, D_, 4 * D_, 2);
    }
}

// round 9
// speedup vs baseline: 1.6934x; 1.6903x over previous
#include <cuda_runtime.h>
#include <cuda_fp16.h>
#include <cstdint>

#define S_   1024
#define B_   2
#define D_   1024
#define H_   16
#define DH_  64
#define L_   4
#define WIN_ 64
#define M_   (S_*B_)   // 2048 token rows

// ---------------- scratch (no allocations allowed) ----------------
__device__ float  g_mod[L_*B_*6*D_];
__device__ __half g_xm [M_*D_];        // LN-modulated activations (fp16)
__device__ __half g_qkv[M_*3*D_];      // qkv projections (fp16)
__device__ __half g_o  [M_*D_];        // attention output (fp16)
__device__ __half g_h  [M_*4*D_];      // MLP hidden (fp16)
// fp16 weight copies
__device__ __half g_wqkv [L_*3*D_*D_];
__device__ __half g_wout [L_*D_*D_];
__device__ __half g_wmlp1[L_*4*D_*D_];
__device__ __half g_wmlp2[L_*D_*4*D_];

__device__ __forceinline__ uint32_t smem_u32(const void* p) {
    uint32_t a; asm("{ .reg .u64 t; cvta.to.shared.u64 t, %1; cvt.u32.u64 %0, t; }" : "=r"(a) : "l"(p));
    return a;
}
__device__ __forceinline__ uint32_t h2u(__half2 h) {
    return *reinterpret_cast<uint32_t*>(&h);
}
#define CP_ASYNC16(dst, src) \
    asm volatile("cp.async.cg.shared.global [%0], [%1], 16;" :: "r"(dst), "l"(src))
#define LDSM4(r0, r1, r2, r3, addr) \
    asm volatile("ldmatrix.sync.aligned.m8n8.x4.shared.b16 {%0,%1,%2,%3}, [%4];" \
        : "=r"(r0), "=r"(r1), "=r"(r2), "=r"(r3) : "r"(addr))
#define LDSM4T(r0, r1, r2, r3, addr) \
    asm volatile("ldmatrix.sync.aligned.m8n8.x4.trans.shared.b16 {%0,%1,%2,%3}, [%4];" \
        : "=r"(r0), "=r"(r1), "=r"(r2), "=r"(r3) : "r"(addr))
#define MMA16816(d0,d1,d2,d3,a0,a1,a2,a3,b0,b1) \
    asm volatile("mma.sync.aligned.m16n8k16.row.col.f32.f16.f16.f32 " \
        "{%0,%1,%2,%3}, {%4,%5,%6,%7}, {%8,%9}, {%0,%1,%2,%3};" \
        : "+f"(d0), "+f"(d1), "+f"(d2), "+f"(d3) \
        : "r"(a0), "r"(a1), "r"(a2), "r"(a3), "r"(b0), "r"(b1))

// ---------------- weight convert fp32 -> fp16 ----------------
__global__ void cvt_kernel(const float* __restrict__ src, __half* __restrict__ dst, int n8) {
    int i = blockIdx.x * blockDim.x + threadIdx.x;
    if (i < n8) {
        float4 v0 = reinterpret_cast<const float4*>(src)[2*i];
        float4 v1 = reinterpret_cast<const float4*>(src)[2*i+1];
        uint4 u;
        u.x = h2u(__floats2half2_rn(v0.x, v0.y));
        u.y = h2u(__floats2half2_rn(v0.z, v0.w));
        u.z = h2u(__floats2half2_rn(v1.x, v1.y));
        u.w = h2u(__floats2half2_rn(v1.z, v1.w));
        reinterpret_cast<uint4*>(dst)[i] = u;
    }
}

// ---------------- adaLN modulation ----------------
__global__ void mod_kernel(const float* __restrict__ c,
                           const float* __restrict__ wada,
                           const float* __restrict__ bada) {
    int tid = threadIdx.x, lane = tid & 31;
    int widx = blockIdx.x * 8 + (tid >> 5);
    int l = widx / (6 * D_), j = widx % (6 * D_);
    const float* wr = wada + ((size_t)l * 6 * D_ + j) * D_;
    float a0 = 0.f, a1 = 0.f;
    for (int k = lane; k < D_; k += 32) {
        float wv = wr[k];
        a0 += wv * fmaxf(c[k], 0.f);
        a1 += wv * fmaxf(c[D_ + k], 0.f);
    }
    #pragma unroll
    for (int off = 16; off; off >>= 1) {
        a0 += __shfl_xor_sync(0xffffffffu, a0, off);
        a1 += __shfl_xor_sync(0xffffffffu, a1, off);
    }
    if (lane == 0) {
        float b = bada[l * 6 * D_ + j];
        g_mod[((size_t)l * B_ + 0) * 6 * D_ + j] = a0 + b;
        g_mod[((size_t)l * B_ + 1) * 6 * D_ + j] = a1 + b;
    }
}

// ---------------- LayerNorm + adaLN modulate -> fp16 ----------------
__global__ void ln_mod_kernel(const float* __restrict__ x,
                              const float* __restrict__ mod,
                              int shOff, int scOff,
                              __half* __restrict__ out) {
    int m = blockIdx.x, tid = threadIdx.x;
    const float4* row = reinterpret_cast<const float4*>(x + (size_t)m * D_);
    float4 v = row[tid];
    float s  = v.x + v.y + v.z + v.w;
    float sq = v.x*v.x + v.y*v.y + v.z*v.z + v.w*v.w;
    __shared__ float rs[8], rq[8];
    #pragma unroll
    for (int off = 16; off; off >>= 1) {
        s  += __shfl_xor_sync(0xffffffffu, s,  off);
        sq += __shfl_xor_sync(0xffffffffu, sq, off);
    }
    int lane = tid & 31, wid = tid >> 5;
    if (lane == 0) { rs[wid] = s; rq[wid] = sq; }
    __syncthreads();
    float ts = 0.f, tq = 0.f;
    #pragma unroll
    for (int i = 0; i < 8; i++) { ts += rs[i]; tq += rq[i]; }
    float mean = ts * (1.f / D_);
    float var  = tq * (1.f / D_) - mean * mean;
    float rstd = rsqrtf(var + 1e-6f);
    int b = m & 1;
    const float4* scp = reinterpret_cast<const float4*>(mod + (size_t)b * 6 * D_ + scOff);
    const float4* shp = reinterpret_cast<const float4*>(mod + (size_t)b * 6 * D_ + shOff);
    float4 sc = scp[tid], sh = shp[tid];
    __half2 h0 = __floats2half2_rn((v.x - mean) * rstd * (1.f + sc.x) + sh.x,
                                   (v.y - mean) * rstd * (1.f + sc.y) + sh.y);
    __half2 h1 = __floats2half2_rn((v.z - mean) * rstd * (1.f + sc.z) + sh.z,
                                   (v.w - mean) * rstd * (1.f + sc.w) + sh.w);
    __half2* op = reinterpret_cast<__half2*>(out + (size_t)m * D_);
    op[tid * 2]     = h0;
    op[tid * 2 + 1] = h1;
}

// ---------------- fp16 GEMM: C[M,N] = A[M,K] @ W[N,K]^T (+ epilogue) ----------------
// mode 0: Cf = acc + bias                      (fp32 out)
// mode 1: Ch = half(relu(acc + bias))          (fp16 out)
// mode 2: Cf = xin + gate * (acc + bias)       (fp32 out, gated residual)
// mode 3: Ch = half(acc + bias)                (fp16 out)
#define GP 72          // smem row pitch in halves (144 B)
template<int TN>
__global__ __launch_bounds__(256, 2)
void gemm_fp16(const __half* __restrict__ A, const __half* __restrict__ W,
               const float* __restrict__ bias,
               float* __restrict__ Cf, __half* __restrict__ Ch,
               const float* __restrict__ xin, const float* __restrict__ mod, int gateOff,
               int N, int K, int mode)
{
    constexpr int NT = TN / 32;
    constexpr int ABYTES = 128 * GP * 2;
    constexpr int BBYTES = TN * GP * 2;
    constexpr int STG = ABYTES + BBYTES;
    extern __shared__ char smraw[];
    uint32_t sbase = smem_u32(smraw);
    int tid = threadIdx.x, lane = tid & 31, w = tid >> 5;
    int warpM = w >> 2, warpN = w & 3;
    int g = lane >> 2, q = lane & 3;
    int bm = blockIdx.y * 128, bn = blockIdx.x * TN;

    uint32_t aoff2 = 2u * (((lane & 7) + (lane & 8)) * GP + ((lane & 16) >> 1));
    uint32_t boff2 = 2u * (((lane & 7) + ((lane & 16) >> 1)) * GP + (lane & 8));

    auto loadStage = [&](int slot, int kidx) {
        int k0 = kidx << 6;
        uint32_t aB = sbase + slot * STG;
        #pragma unroll
        for (int i = 0; i < 4; i++) {
            int seg = tid + i * 256;
            int row = seg >> 3, c = seg & 7;
            CP_ASYNC16(aB + row * (GP*2) + c * 16,
                       A + (size_t)(bm + row) * K + k0 + c * 8);
        }
        #pragma unroll
        for (int i = 0; i < TN / 32; i++) {
            int seg = tid + i * 256;
            int row = seg >> 3, c = seg & 7;
            CP_ASYNC16(aB + ABYTES + row * (GP*2) + c * 16,
                       W + (size_t)(bn + row) * K + k0 + c * 8);
        }
        asm volatile("cp.async.commit_group;");
    };

    float acc[4][NT][4];
    #pragma unroll
    for (int i = 0; i < 4; i++)
        #pragma unroll
        for (int j = 0; j < NT; j++)
            #pragma unroll
            for (int k = 0; k < 4; k++) acc[i][j][k] = 0.f;

    const int T = K >> 6;
    loadStage(0, 0);
    loadStage(1, 1);

    for (int t = 0; t < T; t++) {
        if (t < T - 1) asm volatile("cp.async.wait_group 1;");
        else           asm volatile("cp.async.wait_group 0;");
        __syncthreads();
        if (t + 2 < T) loadStage((t + 2) % 3, t + 2);

        uint32_t aBase = sbase + (t % 3) * STG;
        uint32_t bBase = aBase + ABYTES;
        #pragma unroll
        for (int kk = 0; kk < 4; kk++) {
            uint32_t af[4][4];
            #pragma unroll
            for (int mt = 0; mt < 4; mt++) {
                uint32_t ad = aBase + 2u * ((warpM * 64 + mt * 16) * GP + kk * 16) + aoff2;
                LDSM4(af[mt][0], af[mt][1], af[mt][2], af[mt][3], ad);
            }
            uint32_t bf[NT][2];
            #pragma unroll
            for (int nb = 0; nb < NT / 2; nb++) {
                uint32_t bd = bBase + 2u * ((warpN * (TN/4) + nb * 16) * GP + kk * 16) + boff2;
                uint32_t r0, r1, r2, r3;
                LDSM4(r0, r1, r2, r3, bd);
                bf[2*nb][0] = r0;   bf[2*nb][1] = r1;
                bf[2*nb+1][0] = r2; bf[2*nb+1][1] = r3;
            }
            #pragma unroll
            for (int mt = 0; mt < 4; mt++)
                #pragma unroll
                for (int nt = 0; nt < NT; nt++)
                    MMA16816(acc[mt][nt][0], acc[mt][nt][1], acc[mt][nt][2], acc[mt][nt][3],
                             af[mt][0], af[mt][1], af[mt][2], af[mt][3],
                             bf[nt][0], bf[nt][1]);
        }
    }

    // epilogue
    float bz[NT][2], gz[2][NT][2];
    #pragma unroll
    for (int nt = 0; nt < NT; nt++) {
        int col = bn + warpN * (TN/4) + nt * 8 + q * 2;
        bz[nt][0] = bias[col];
        bz[nt][1] = bias[col + 1];
        if (mode == 2) {
            gz[0][nt][0] = mod[gateOff + col];
            gz[0][nt][1] = mod[gateOff + col + 1];
            gz[1][nt][0] = mod[6 * D_ + gateOff + col];
            gz[1][nt][1] = mod[6 * D_ + gateOff + col + 1];
        }
    }
    #pragma unroll
    for (int mt = 0; mt < 4; mt++) {
        #pragma unroll
        for (int half = 0; half < 2; half++) {
            int r = warpM * 64 + mt * 16 + g + half * 8;
            size_t rowoff = (size_t)(bm + r) * N;
            int par = r & 1;
            #pragma unroll
            for (int nt = 0; nt < NT; nt++) {
                int col = bn + warpN * (TN/4) + nt * 8 + q * 2;
                float v0 = acc[mt][nt][half * 2 + 0] + bz[nt][0];
                float v1 = acc[mt][nt][half * 2 + 1] + bz[nt][1];
                if (mode == 1) {
                    __half2 hv = __floats2half2_rn(fmaxf(v0, 0.f), fmaxf(v1, 0.f));
                    *reinterpret_cast<__half2*>(Ch + rowoff + col) = hv;
                } else if (mode == 3) {
                    __half2 hv = __floats2half2_rn(v0, v1);
                    *reinterpret_cast<__half2*>(Ch + rowoff + col) = hv;
                } else if (mode == 2) {
                    float2 xi = *reinterpret_cast<const float2*>(xin + rowoff + col);
                    float2 r2;
                    r2.x = xi.x + gz[par][nt][0] * v0;
                    r2.y = xi.y + gz[par][nt][1] * v1;
                    *reinterpret_cast<float2*>(Cf + rowoff + col) = r2;
                } else {
                    float2 r2; r2.x = v0; r2.y = v1;
                    *reinterpret_cast<float2*>(Cf + rowoff + col) = r2;
                }
            }
        }
    }
}

// ---------------- tensor-core windowed flash attention ----------------
// block = (64 queries, b, h), 4 warps; window = 192 keys [s0-64, s0+127]
#define AP 72                      // smem pitch (halves)
#define ASMEM ((64 + 192 + 192) * AP * 2)   // Q + K + V = 64512 B
__global__ __launch_bounds__(128)
void attn_tc(const __half* __restrict__ qkv, __half* __restrict__ o) {
    extern __shared__ char asm_raw[];
    uint32_t sb = smem_u32(asm_raw);
    int tid = threadIdx.x, lane = tid & 31, w = tid >> 5;
    int g = lane >> 2, q = lane & 3;
    int bh = blockIdx.y;
    int b = bh / H_, h = bh % H_;
    int s0 = blockIdx.x * 64;
    int kbase = s0 - 64;

    // ---- load Q (64 rows), K,V (192 rows each) ----
    #pragma unroll
    for (int i = 0; i < 4; i++) {
        int seg = tid + i * 128;
        int r = seg >> 3, c = seg & 7;
        CP_ASYNC16(sb + (r * AP + c * 8) * 2,
                   qkv + ((size_t)((s0 + r) * B_ + b)) * (3 * D_) + h * 64 + c * 8);
    }
    #pragma unroll
    for (int i = 0; i < 12; i++) {
        int seg = tid + i * 128;
        int r = seg >> 3, c = seg & 7;
        int t = kbase + r; t = t < 0 ? 0 : (t > S_ - 1 ? S_ - 1 : t);
        const __half* src = qkv + ((size_t)(t * B_ + b)) * (3 * D_) + D_ + h * 64 + c * 8;
        CP_ASYNC16(sb + ((64 + r) * AP + c * 8) * 2, src);
        CP_ASYNC16(sb + ((256 + r) * AP + c * 8) * 2, src + D_);
    }
    asm volatile("cp.async.commit_group;");
    asm volatile("cp.async.wait_group 0;");
    __syncthreads();

    uint32_t aoff = 2u * (((lane & 7) + (lane & 8)) * AP + ((lane & 16) >> 1));
    uint32_t boff = 2u * (((lane & 7) + ((lane & 16) >> 1)) * AP + (lane & 8));
    uint32_t voff = 2u * ((lane & 15) * AP + (lane >> 4) * 8);

    // Q fragments (held in regs for all 12 chunks)
    uint32_t qa[4][4];
    #pragma unroll
    for (int kk = 0; kk < 4; kk++)
        LDSM4(qa[kk][0], qa[kk][1], qa[kk][2], qa[kk][3],
              sb + 2u * ((w * 16) * AP + kk * 16) + aoff);

    float m0 = 0.f, m1 = 0.f, l0 = 0.f, l1 = 0.f;
    float acc[8][4];
    #pragma unroll
    for (int i = 0; i < 8; i++)
        #pragma unroll
        for (int j = 0; j < 4; j++) acc[i][j] = 0.f;

    int r0 = s0 + w * 16 + g;     // query rows for this lane
    int r1 = r0 + 8;

    for (int ch = 0; ch < 12; ch++) {
        int krow = ch * 16;
        // ---- scores: Q(16x64) @ K(16keys x 64)^T ----
        float sc[2][4];
        #pragma unroll
        for (int nt = 0; nt < 2; nt++)
            #pragma unroll
            for (int i = 0; i < 4; i++) sc[nt][i] = 0.f;
        #pragma unroll
        for (int kk = 0; kk < 4; kk++) {
            uint32_t f0, f1, f2, f3;
            LDSM4(f0, f1, f2, f3, sb + 2u * ((64 + krow) * AP + kk * 16) + boff);
            MMA16816(sc[0][0], sc[0][1], sc[0][2], sc[0][3],
                     qa[kk][0], qa[kk][1], qa[kk][2], qa[kk][3], f0, f1);
            MMA16816(sc[1][0], sc[1][1], sc[1][2], sc[1][3],
                     qa[kk][0], qa[kk][1], qa[kk][2], qa[kk][3], f2, f3);
        }
        // ---- scale + mask ----
        #pragma unroll
        for (int nt = 0; nt < 2; nt++) {
            #pragma unroll
            for (int i = 0; i < 2; i++) {
                int t = kbase + krow + nt * 8 + q * 2 + i;
                bool okT = (t >= 0) && (t < S_);
                int d0 = t - r0; if (d0 < 0) d0 = -d0;
                int d1 = t - r1; if (d1 < 0) d1 = -d1;
                sc[nt][i]     = (okT && d0 <= WIN_) ? sc[nt][i]     * 0.125f : -1e30f;
                sc[nt][2 + i] = (okT && d1 <= WIN_) ? sc[nt][2 + i] * 0.125f : -1e30f;
            }
        }
        // ---- online softmax (rows r0, r1) ----
        float rm0 = fmaxf(fmaxf(sc[0][0], sc[0][1]), fmaxf(sc[1][0], sc[1][1]));
        float rm1 = fmaxf(fmaxf(sc[0][2], sc[0][3]), fmaxf(sc[1][2], sc[1][3]));
        rm0 = fmaxf(rm0, __shfl_xor_sync(0xffffffffu, rm0, 1));
        rm0 = fmaxf(rm0, __shfl_xor_sync(0xffffffffu, rm0, 2));
        rm1 = fmaxf(rm1, __shfl_xor_sync(0xffffffffu, rm1, 1));
        rm1 = fmaxf(rm1, __shfl_xor_sync(0xffffffffu, rm1, 2));
        float m0n = fmaxf(m0, rm0), m1n = fmaxf(m1, rm1);
        float c0 = __expf(m0 - m0n), c1 = __expf(m1 - m1n);
        float p00 = __expf(sc[0][0] - m0n), p01 = __expf(sc[0][1] - m0n);
        float p10 = __expf(sc[1][0] - m0n), p11 = __expf(sc[1][1] - m0n);
        float p02 = __expf(sc[0][2] - m1n), p03 = __expf(sc[0][3] - m1n);
        float p12 = __expf(sc[1][2] - m1n), p13 = __expf(sc[1][3] - m1n);
        float rs0 = (p00 + p01) + (p10 + p11);
        float rs1 = (p02 + p03) + (p12 + p13);
        rs0 += __shfl_xor_sync(0xffffffffu, rs0, 1);
        rs0 += __shfl_xor_sync(0xffffffffu, rs0, 2);
        rs1 += __shfl_xor_sync(0xffffffffu, rs1, 1);
        rs1 += __shfl_xor_sync(0xffffffffu, rs1, 2);
        l0 = l0 * c0 + rs0;
        l1 = l1 * c1 + rs1;
        m0 = m0n; m1 = m1n;
        #pragma unroll
        for (int nt = 0; nt < 8; nt++) {
            acc[nt][0] *= c0; acc[nt][1] *= c0;
            acc[nt][2] *= c1; acc[nt][3] *= c1;
        }
        // ---- P fragments (fp16) ----
        uint32_t pa0 = h2u(__floats2half2_rn(p00, p01));
        uint32_t pa1 = h2u(__floats2half2_rn(p02, p03));
        uint32_t pa2 = h2u(__floats2half2_rn(p10, p11));
        uint32_t pa3 = h2u(__floats2half2_rn(p12, p13));
        // ---- PV: P(16x16) @ V(16keys x 64) ----
        #pragma unroll
        for (int dv = 0; dv < 4; dv++) {
            uint32_t v0, v1, v2, v3;
            LDSM4T(v0, v1, v2, v3, sb + 2u * ((256 + krow) * AP + dv * 16) + voff);
            MMA16816(acc[2*dv][0], acc[2*dv][1], acc[2*dv][2], acc[2*dv][3],
                     pa0, pa1, pa2, pa3, v0, v1);
            MMA16816(acc[2*dv+1][0], acc[2*dv+1][1], acc[2*dv+1][2], acc[2*dv+1][3],
                     pa0, pa1, pa2, pa3, v2, v3);
        }
    }

    // ---- normalize + store ----
    float inv0 = 1.f / l0, inv1 = 1.f / l1;
    #pragma unroll
    for (int nt = 0; nt < 8; nt++) {
        int col = h * 64 + nt * 8 + q * 2;
        __half2 h0 = __floats2half2_rn(acc[nt][0] * inv0, acc[nt][1] * inv0);
        __half2 h1 = __floats2half2_rn(acc[nt][2] * inv1, acc[nt][3] * inv1);
        *reinterpret_cast<__half2*>(o + ((size_t)(r0 * B_ + b)) * D_ + col) = h0;
        *reinterpret_cast<__half2*>(o + ((size_t)(r1 * B_ + b)) * D_ + col) = h1;
    }
}

// ---------------- launcher ----------------
extern "C" void kernel_launch(void* const* d_in, const int* in_sizes, int n_in,
                              void* d_out, int out_size) {
    const float* x_in   = (const float*)d_in[0];
    const float* c      = (const float*)d_in[1];
    const float* w_qkv  = (const float*)d_in[2];
    const float* b_qkv  = (const float*)d_in[3];
    const float* w_out  = (const float*)d_in[4];
    const float* b_out  = (const float*)d_in[5];
    const float* w_mlp1 = (const float*)d_in[6];
    const float* b_mlp1 = (const float*)d_in[7];
    const float* w_mlp2 = (const float*)d_in[8];
    const float* b_mlp2 = (const float*)d_in[9];
    const float* w_ada  = (const float*)d_in[10];
    const float* b_ada  = (const float*)d_in[11];
    float* x = (float*)d_out;

    float  *mod;
    __half *xm, *qkv, *o, *h, *wq, *wo, *w1, *w2;
    cudaGetSymbolAddress((void**)&mod, g_mod);
    cudaGetSymbolAddress((void**)&xm,  g_xm);
    cudaGetSymbolAddress((void**)&qkv, g_qkv);
    cudaGetSymbolAddress((void**)&o,   g_o);
    cudaGetSymbolAddress((void**)&h,   g_h);
    cudaGetSymbolAddress((void**)&wq,  g_wqkv);
    cudaGetSymbolAddress((void**)&wo,  g_wout);
    cudaGetSymbolAddress((void**)&w1,  g_wmlp1);
    cudaGetSymbolAddress((void**)&w2,  g_wmlp2);

    const int smem128 = 3 * (128 * GP * 2 + 128 * GP * 2);  // 110592
    const int smem64  = 3 * (128 * GP * 2 + 64  * GP * 2);  // 82944
    cudaFuncSetAttribute(gemm_fp16<128>, cudaFuncAttributeMaxDynamicSharedMemorySize, smem128);
    cudaFuncSetAttribute(gemm_fp16<64>,  cudaFuncAttributeMaxDynamicSharedMemorySize, smem64);
    cudaFuncSetAttribute(attn_tc,        cudaFuncAttributeMaxDynamicSharedMemorySize, ASMEM);

    cudaMemcpyAsync(x, x_in, (size_t)M_ * D_ * sizeof(float), cudaMemcpyDeviceToDevice);

    // weight convert fp32 -> fp16
    {
        int n;
        n = L_*3*D_*D_/8;  cvt_kernel<<<(n+255)/256, 256>>>(w_qkv,  wq, n);
        n = L_*D_*D_/8;    cvt_kernel<<<(n+255)/256, 256>>>(w_out,  wo, n);
        n = L_*4*D_*D_/8;  cvt_kernel<<<(n+255)/256, 256>>>(w_mlp1, w1, n);
        n = L_*D_*4*D_/8;  cvt_kernel<<<(n+255)/256, 256>>>(w_mlp2, w2, n);
    }

    mod_kernel<<<(L_ * 6 * D_) / 8, 256>>>(c, w_ada, b_ada);

    for (int l = 0; l < L_; l++) {
        const float* modl = mod + (size_t)l * B_ * 6 * D_;
        // --- attention branch ---
        ln_mod_kernel<<<M_, 256>>>(x, modl, 0, D_, xm);
        gemm_fp16<128><<<dim3(3 * D_ / 128, M_ / 128), 256, smem128>>>(
            xm, wq + (size_t)l * 3 * D_ * D_, b_qkv + (size_t)l * 3 * D_,
            nullptr, qkv, nullptr, nullptr, 0, 3 * D_, D_, 3);
        attn_tc<<<dim3(S_ / 64, B_ * H_), 128, ASMEM>>>(qkv, o);
        gemm_fp16<64><<<dim3(D_ / 64, M_ / 128), 256, smem64>>>(
            o, wo + (size_t)l * D_ * D_, b_out + (size_t)l * D_,
            x, nullptr, x, modl, 2 * D_, D_, D_, 2);
        // --- MLP branch ---
        ln_mod_kernel<<<M_, 256>>>(x, modl, 3 * D_, 4 * D_, xm);
        gemm_fp16<128><<<dim3(4 * D_ / 128, M_ / 128), 256, smem128>>>(
            xm, w1 + (size_t)l * 4 * D_ * D_, b_mlp1 + (size_t)l * 4 * D_,
            nullptr, h, nullptr, nullptr, 0, 4 * D_, D_, 1);
        gemm_fp16<64><<<dim3(D_ / 64, M_ / 128), 256, smem64>>>(
            h, w2 + (size_t)l * D_ * 4 * D_, b_mlp2 + (size_t)l * D_,
            x, nullptr, x, modl, 5 * D_, D_, 4 * D_, 2);
    }
}

// round 10
// speedup vs baseline: 1.8355x; 1.0839x over previous
#include <cuda_runtime.h>
#include <cuda_fp16.h>
#include <cstdint>

#define S_   1024
#define B_   2
#define D_   1024
#define H_   16
#define DH_  64
#define L_   4
#define WIN_ 64
#define M_   (S_*B_)   // 2048 token rows

// ---------------- scratch (no allocations allowed) ----------------
__device__ float  g_mod[L_*B_*6*D_];
__device__ __half g_xm [M_*D_];
__device__ __half g_qkv[M_*3*D_];
__device__ __half g_o  [M_*D_];
__device__ __half g_h  [M_*4*D_];
__device__ __half g_wqkv [L_*3*D_*D_];
__device__ __half g_wout [L_*D_*D_];
__device__ __half g_wmlp1[L_*4*D_*D_];
__device__ __half g_wmlp2[L_*D_*4*D_];

__device__ __forceinline__ uint32_t smem_u32(const void* p) {
    uint32_t a; asm("{ .reg .u64 t; cvta.to.shared.u64 t, %1; cvt.u32.u64 %0, t; }" : "=r"(a) : "l"(p));
    return a;
}
__device__ __forceinline__ uint32_t h2u(__half2 h) {
    return *reinterpret_cast<uint32_t*>(&h);
}
#define CP_ASYNC16(dst, src) \
    asm volatile("cp.async.cg.shared.global [%0], [%1], 16;" :: "r"(dst), "l"(src))
#define LDSM4(r0, r1, r2, r3, addr) \
    asm volatile("ldmatrix.sync.aligned.m8n8.x4.shared.b16 {%0,%1,%2,%3}, [%4];" \
        : "=r"(r0), "=r"(r1), "=r"(r2), "=r"(r3) : "r"(addr))
#define LDSM4T(r0, r1, r2, r3, addr) \
    asm volatile("ldmatrix.sync.aligned.m8n8.x4.trans.shared.b16 {%0,%1,%2,%3}, [%4];" \
        : "=r"(r0), "=r"(r1), "=r"(r2), "=r"(r3) : "r"(addr))
#define MMA16816(d0,d1,d2,d3,a0,a1,a2,a3,b0,b1) \
    asm volatile("mma.sync.aligned.m16n8k16.row.col.f32.f16.f16.f32 " \
        "{%0,%1,%2,%3}, {%4,%5,%6,%7}, {%8,%9}, {%0,%1,%2,%3};" \
        : "+f"(d0), "+f"(d1), "+f"(d2), "+f"(d3) \
        : "r"(a0), "r"(a1), "r"(a2), "r"(a3), "r"(b0), "r"(b1))

// ---------------- weight convert fp32 -> fp16 ----------------
__global__ void cvt_kernel(const float* __restrict__ src, __half* __restrict__ dst, int n8) {
    int i = blockIdx.x * blockDim.x + threadIdx.x;
    if (i < n8) {
        float4 v0 = reinterpret_cast<const float4*>(src)[2*i];
        float4 v1 = reinterpret_cast<const float4*>(src)[2*i+1];
        uint4 u;
        u.x = h2u(__floats2half2_rn(v0.x, v0.y));
        u.y = h2u(__floats2half2_rn(v0.z, v0.w));
        u.z = h2u(__floats2half2_rn(v1.x, v1.y));
        u.w = h2u(__floats2half2_rn(v1.z, v1.w));
        reinterpret_cast<uint4*>(dst)[i] = u;
    }
}

// ---------------- adaLN modulation ----------------
__global__ void mod_kernel(const float* __restrict__ c,
                           const float* __restrict__ wada,
                           const float* __restrict__ bada) {
    int tid = threadIdx.x, lane = tid & 31;
    int widx = blockIdx.x * 8 + (tid >> 5);
    int l = widx / (6 * D_), j = widx % (6 * D_);
    const float* wr = wada + ((size_t)l * 6 * D_ + j) * D_;
    float a0 = 0.f, a1 = 0.f;
    for (int k = lane; k < D_; k += 32) {
        float wv = wr[k];
        a0 += wv * fmaxf(c[k], 0.f);
        a1 += wv * fmaxf(c[D_ + k], 0.f);
    }
    #pragma unroll
    for (int off = 16; off; off >>= 1) {
        a0 += __shfl_xor_sync(0xffffffffu, a0, off);
        a1 += __shfl_xor_sync(0xffffffffu, a1, off);
    }
    if (lane == 0) {
        float b = bada[l * 6 * D_ + j];
        g_mod[((size_t)l * B_ + 0) * 6 * D_ + j] = a0 + b;
        g_mod[((size_t)l * B_ + 1) * 6 * D_ + j] = a1 + b;
    }
}

// ---------------- LayerNorm + adaLN modulate -> fp16 ----------------
__global__ void ln_mod_kernel(const float* __restrict__ x,
                              const float* __restrict__ mod,
                              int shOff, int scOff,
                              __half* __restrict__ out) {
    int m = blockIdx.x, tid = threadIdx.x;
    const float4* row = reinterpret_cast<const float4*>(x + (size_t)m * D_);
    float4 v = row[tid];
    float s  = v.x + v.y + v.z + v.w;
    float sq = v.x*v.x + v.y*v.y + v.z*v.z + v.w*v.w;
    __shared__ float rs[8], rq[8];
    #pragma unroll
    for (int off = 16; off; off >>= 1) {
        s  += __shfl_xor_sync(0xffffffffu, s,  off);
        sq += __shfl_xor_sync(0xffffffffu, sq, off);
    }
    int lane = tid & 31, wid = tid >> 5;
    if (lane == 0) { rs[wid] = s; rq[wid] = sq; }
    __syncthreads();
    float ts = 0.f, tq = 0.f;
    #pragma unroll
    for (int i = 0; i < 8; i++) { ts += rs[i]; tq += rq[i]; }
    float mean = ts * (1.f / D_);
    float var  = tq * (1.f / D_) - mean * mean;
    float rstd = rsqrtf(var + 1e-6f);
    int b = m & 1;
    const float4* scp = reinterpret_cast<const float4*>(mod + (size_t)b * 6 * D_ + scOff);
    const float4* shp = reinterpret_cast<const float4*>(mod + (size_t)b * 6 * D_ + shOff);
    float4 sc = scp[tid], sh = shp[tid];
    __half2 h0 = __floats2half2_rn((v.x - mean) * rstd * (1.f + sc.x) + sh.x,
                                   (v.y - mean) * rstd * (1.f + sc.y) + sh.y);
    __half2 h1 = __floats2half2_rn((v.z - mean) * rstd * (1.f + sc.z) + sh.z,
                                   (v.w - mean) * rstd * (1.f + sc.w) + sh.w);
    __half2* op = reinterpret_cast<__half2*>(out + (size_t)m * D_);
    op[tid * 2]     = h0;
    op[tid * 2 + 1] = h1;
}

// ---------------- fp16 GEMM: 4 warps, warp tile 64x64, CTA 128x128 ----------------
// mode 0: Cf = acc + bias
// mode 1: Ch = half(relu(acc + bias))
// mode 2: Cf = xin + gate * (acc + bias)
// mode 3: Ch = half(acc + bias)
#define GP 72          // smem row pitch in halves (144 B)
#define GABYTES (128 * GP * 2)          // 18432
#define GSTG    (2 * GABYTES)           // 36864 (A + B)
__global__ __launch_bounds__(128, 2)
void gemm_fp16(const __half* __restrict__ A, const __half* __restrict__ W,
               const float* __restrict__ bias,
               float* __restrict__ Cf, __half* __restrict__ Ch,
               const float* __restrict__ xin, const float* __restrict__ mod, int gateOff,
               int N, int K, int mode)
{
    extern __shared__ char smraw[];
    uint32_t sbase = smem_u32(smraw);
    int tid = threadIdx.x, lane = tid & 31, w = tid >> 5;
    int warpM = w >> 1, warpN = w & 1;          // 2 x 2, warp tile 64x64
    int g = lane >> 2, q = lane & 3;
    int bm = blockIdx.y * 128, bn = blockIdx.x * 128;

    uint32_t aoff2 = 2u * (((lane & 7) + (lane & 8)) * GP + ((lane & 16) >> 1));
    uint32_t boff2 = 2u * (((lane & 7) + ((lane & 16) >> 1)) * GP + (lane & 8));

    auto loadStage = [&](int slot, int kidx) {
        int k0 = kidx << 6;
        uint32_t aB = sbase + slot * GSTG;
        #pragma unroll
        for (int i = 0; i < 8; i++) {
            int seg = tid + i * 128;
            int row = seg >> 3, c = seg & 7;
            CP_ASYNC16(aB + row * (GP*2) + c * 16,
                       A + (size_t)(bm + row) * K + k0 + c * 8);
        }
        #pragma unroll
        for (int i = 0; i < 8; i++) {
            int seg = tid + i * 128;
            int row = seg >> 3, c = seg & 7;
            CP_ASYNC16(aB + GABYTES + row * (GP*2) + c * 16,
                       W + (size_t)(bn + row) * K + k0 + c * 8);
        }
        asm volatile("cp.async.commit_group;");
    };

    float acc[4][8][4];
    #pragma unroll
    for (int i = 0; i < 4; i++)
        #pragma unroll
        for (int j = 0; j < 8; j++)
            #pragma unroll
            for (int k = 0; k < 4; k++) acc[i][j][k] = 0.f;

    const int T = K >> 6;
    loadStage(0, 0);
    loadStage(1, 1);

    for (int t = 0; t < T; t++) {
        if (t < T - 1) asm volatile("cp.async.wait_group 1;");
        else           asm volatile("cp.async.wait_group 0;");
        __syncthreads();
        if (t + 2 < T) loadStage((t + 2) % 3, t + 2);

        uint32_t aBase = sbase + (t % 3) * GSTG;
        uint32_t bBase = aBase + GABYTES;
        #pragma unroll
        for (int kk = 0; kk < 4; kk++) {
            uint32_t af[4][4];
            #pragma unroll
            for (int mt = 0; mt < 4; mt++) {
                uint32_t ad = aBase + 2u * ((warpM * 64 + mt * 16) * GP + kk * 16) + aoff2;
                LDSM4(af[mt][0], af[mt][1], af[mt][2], af[mt][3], ad);
            }
            uint32_t bf[8][2];
            #pragma unroll
            for (int nb = 0; nb < 4; nb++) {
                uint32_t bd = bBase + 2u * ((warpN * 64 + nb * 16) * GP + kk * 16) + boff2;
                uint32_t r0, r1, r2, r3;
                LDSM4(r0, r1, r2, r3, bd);
                bf[2*nb][0] = r0;   bf[2*nb][1] = r1;
                bf[2*nb+1][0] = r2; bf[2*nb+1][1] = r3;
            }
            #pragma unroll
            for (int mt = 0; mt < 4; mt++)
                #pragma unroll
                for (int nt = 0; nt < 8; nt++)
                    MMA16816(acc[mt][nt][0], acc[mt][nt][1], acc[mt][nt][2], acc[mt][nt][3],
                             af[mt][0], af[mt][1], af[mt][2], af[mt][3],
                             bf[nt][0], bf[nt][1]);
        }
    }

    // epilogue
    float bz[8][2], gz[2][8][2];
    #pragma unroll
    for (int nt = 0; nt < 8; nt++) {
        int col = bn + warpN * 64 + nt * 8 + q * 2;
        bz[nt][0] = bias[col];
        bz[nt][1] = bias[col + 1];
        if (mode == 2) {
            gz[0][nt][0] = mod[gateOff + col];
            gz[0][nt][1] = mod[gateOff + col + 1];
            gz[1][nt][0] = mod[6 * D_ + gateOff + col];
            gz[1][nt][1] = mod[6 * D_ + gateOff + col + 1];
        }
    }
    #pragma unroll
    for (int mt = 0; mt < 4; mt++) {
        #pragma unroll
        for (int half = 0; half < 2; half++) {
            int r = warpM * 64 + mt * 16 + g + half * 8;
            size_t rowoff = (size_t)(bm + r) * N;
            int par = r & 1;
            #pragma unroll
            for (int nt = 0; nt < 8; nt++) {
                int col = bn + warpN * 64 + nt * 8 + q * 2;
                float v0 = acc[mt][nt][half * 2 + 0] + bz[nt][0];
                float v1 = acc[mt][nt][half * 2 + 1] + bz[nt][1];
                if (mode == 1) {
                    __half2 hv = __floats2half2_rn(fmaxf(v0, 0.f), fmaxf(v1, 0.f));
                    *reinterpret_cast<__half2*>(Ch + rowoff + col) = hv;
                } else if (mode == 3) {
                    __half2 hv = __floats2half2_rn(v0, v1);
                    *reinterpret_cast<__half2*>(Ch + rowoff + col) = hv;
                } else if (mode == 2) {
                    float2 xi = *reinterpret_cast<const float2*>(xin + rowoff + col);
                    float2 r2;
                    r2.x = xi.x + gz[par][nt][0] * v0;
                    r2.y = xi.y + gz[par][nt][1] * v1;
                    *reinterpret_cast<float2*>(Cf + rowoff + col) = r2;
                } else {
                    float2 r2; r2.x = v0; r2.y = v1;
                    *reinterpret_cast<float2*>(Cf + rowoff + col) = r2;
                }
            }
        }
    }
}

// ---------------- tensor-core windowed flash attention ----------------
// block = (128 queries, b, h), 8 warps; window = 256 keys [s0-64, s0+191]
#define AP 72
#define ASMEM ((128 + 256 + 256) * AP * 2)   // Q + K + V = 92160 B
__global__ __launch_bounds__(256)
void attn_tc(const __half* __restrict__ qkv, __half* __restrict__ o) {
    extern __shared__ char asm_raw[];
    uint32_t sb = smem_u32(asm_raw);
    int tid = threadIdx.x, lane = tid & 31, w = tid >> 5;
    int g = lane >> 2, q = lane & 3;
    int bh = blockIdx.y;
    int b = bh / H_, h = bh % H_;
    int s0 = blockIdx.x * 128;
    int kbase = s0 - 64;

    // ---- load Q (128 rows), K,V (256 rows each) ----
    #pragma unroll
    for (int i = 0; i < 4; i++) {
        int seg = tid + i * 256;
        int r = seg >> 3, c = seg & 7;
        CP_ASYNC16(sb + (r * AP + c * 8) * 2,
                   qkv + ((size_t)((s0 + r) * B_ + b)) * (3 * D_) + h * 64 + c * 8);
    }
    #pragma unroll
    for (int i = 0; i < 8; i++) {
        int seg = tid + i * 256;
        int r = seg >> 3, c = seg & 7;
        int t = kbase + r; t = t < 0 ? 0 : (t > S_ - 1 ? S_ - 1 : t);
        const __half* src = qkv + ((size_t)(t * B_ + b)) * (3 * D_) + D_ + h * 64 + c * 8;
        CP_ASYNC16(sb + ((128 + r) * AP + c * 8) * 2, src);
        CP_ASYNC16(sb + ((384 + r) * AP + c * 8) * 2, src + D_);
    }
    asm volatile("cp.async.commit_group;");
    asm volatile("cp.async.wait_group 0;");
    __syncthreads();

    uint32_t aoff = 2u * (((lane & 7) + (lane & 8)) * AP + ((lane & 16) >> 1));
    uint32_t boff = 2u * (((lane & 7) + ((lane & 16) >> 1)) * AP + (lane & 8));
    uint32_t voff = 2u * ((lane & 15) * AP + (lane >> 4) * 8);

    uint32_t qa[4][4];
    #pragma unroll
    for (int kk = 0; kk < 4; kk++)
        LDSM4(qa[kk][0], qa[kk][1], qa[kk][2], qa[kk][3],
              sb + 2u * ((w * 16) * AP + kk * 16) + aoff);

    float m0 = 0.f, m1 = 0.f, l0 = 0.f, l1 = 0.f;
    float acc[8][4];
    #pragma unroll
    for (int i = 0; i < 8; i++)
        #pragma unroll
        for (int j = 0; j < 4; j++) acc[i][j] = 0.f;

    int r0 = s0 + w * 16 + g;
    int r1 = r0 + 8;

    for (int ch = 0; ch < 16; ch++) {
        int krow = ch * 16;
        float sc[2][4];
        #pragma unroll
        for (int nt = 0; nt < 2; nt++)
            #pragma unroll
            for (int i = 0; i < 4; i++) sc[nt][i] = 0.f;
        #pragma unroll
        for (int kk = 0; kk < 4; kk++) {
            uint32_t f0, f1, f2, f3;
            LDSM4(f0, f1, f2, f3, sb + 2u * ((128 + krow) * AP + kk * 16) + boff);
            MMA16816(sc[0][0], sc[0][1], sc[0][2], sc[0][3],
                     qa[kk][0], qa[kk][1], qa[kk][2], qa[kk][3], f0, f1);
            MMA16816(sc[1][0], sc[1][1], sc[1][2], sc[1][3],
                     qa[kk][0], qa[kk][1], qa[kk][2], qa[kk][3], f2, f3);
        }
        #pragma unroll
        for (int nt = 0; nt < 2; nt++) {
            #pragma unroll
            for (int i = 0; i < 2; i++) {
                int t = kbase + krow + nt * 8 + q * 2 + i;
                bool okT = (t >= 0) && (t < S_);
                int d0 = t - r0; if (d0 < 0) d0 = -d0;
                int d1 = t - r1; if (d1 < 0) d1 = -d1;
                sc[nt][i]     = (okT && d0 <= WIN_) ? sc[nt][i]     * 0.125f : -1e30f;
                sc[nt][2 + i] = (okT && d1 <= WIN_) ? sc[nt][2 + i] * 0.125f : -1e30f;
            }
        }
        float rm0 = fmaxf(fmaxf(sc[0][0], sc[0][1]), fmaxf(sc[1][0], sc[1][1]));
        float rm1 = fmaxf(fmaxf(sc[0][2], sc[0][3]), fmaxf(sc[1][2], sc[1][3]));
        rm0 = fmaxf(rm0, __shfl_xor_sync(0xffffffffu, rm0, 1));
        rm0 = fmaxf(rm0, __shfl_xor_sync(0xffffffffu, rm0, 2));
        rm1 = fmaxf(rm1, __shfl_xor_sync(0xffffffffu, rm1, 1));
        rm1 = fmaxf(rm1, __shfl_xor_sync(0xffffffffu, rm1, 2));
        float m0n = fmaxf(m0, rm0), m1n = fmaxf(m1, rm1);
        float c0 = __expf(m0 - m0n), c1 = __expf(m1 - m1n);
        float p00 = __expf(sc[0][0] - m0n), p01 = __expf(sc[0][1] - m0n);
        float p10 = __expf(sc[1][0] - m0n), p11 = __expf(sc[1][1] - m0n);
        float p02 = __expf(sc[0][2] - m1n), p03 = __expf(sc[0][3] - m1n);
        float p12 = __expf(sc[1][2] - m1n), p13 = __expf(sc[1][3] - m1n);
        float rs0 = (p00 + p01) + (p10 + p11);
        float rs1 = (p02 + p03) + (p12 + p13);
        rs0 += __shfl_xor_sync(0xffffffffu, rs0, 1);
        rs0 += __shfl_xor_sync(0xffffffffu, rs0, 2);
        rs1 += __shfl_xor_sync(0xffffffffu, rs1, 1);
        rs1 += __shfl_xor_sync(0xffffffffu, rs1, 2);
        l0 = l0 * c0 + rs0;
        l1 = l1 * c1 + rs1;
        m0 = m0n; m1 = m1n;
        #pragma unroll
        for (int nt = 0; nt < 8; nt++) {
            acc[nt][0] *= c0; acc[nt][1] *= c0;
            acc[nt][2] *= c1; acc[nt][3] *= c1;
        }
        uint32_t pa0 = h2u(__floats2half2_rn(p00, p01));
        uint32_t pa1 = h2u(__floats2half2_rn(p02, p03));
        uint32_t pa2 = h2u(__floats2half2_rn(p10, p11));
        uint32_t pa3 = h2u(__floats2half2_rn(p12, p13));
        #pragma unroll
        for (int dv = 0; dv < 4; dv++) {
            uint32_t v0, v1, v2, v3;
            LDSM4T(v0, v1, v2, v3, sb + 2u * ((384 + krow) * AP + dv * 16) + voff);
            MMA16816(acc[2*dv][0], acc[2*dv][1], acc[2*dv][2], acc[2*dv][3],
                     pa0, pa1, pa2, pa3, v0, v1);
            MMA16816(acc[2*dv+1][0], acc[2*dv+1][1], acc[2*dv+1][2], acc[2*dv+1][3],
                     pa0, pa1, pa2, pa3, v2, v3);
        }
    }

    float inv0 = 1.f / l0, inv1 = 1.f / l1;
    #pragma unroll
    for (int nt = 0; nt < 8; nt++) {
        int col = h * 64 + nt * 8 + q * 2;
        __half2 h0 = __floats2half2_rn(acc[nt][0] * inv0, acc[nt][1] * inv0);
        __half2 h1 = __floats2half2_rn(acc[nt][2] * inv1, acc[nt][3] * inv1);
        *reinterpret_cast<__half2*>(o + ((size_t)(r0 * B_ + b)) * D_ + col) = h0;
        *reinterpret_cast<__half2*>(o + ((size_t)(r1 * B_ + b)) * D_ + col) = h1;
    }
}

// ---------------- launcher ----------------
extern "C" void kernel_launch(void* const* d_in, const int* in_sizes, int n_in,
                              void* d_out, int out_size) {
    const float* x_in   = (const float*)d_in[0];
    const float* c      = (const float*)d_in[1];
    const float* w_qkv  = (const float*)d_in[2];
    const float* b_qkv  = (const float*)d_in[3];
    const float* w_out  = (const float*)d_in[4];
    const float* b_out  = (const float*)d_in[5];
    const float* w_mlp1 = (const float*)d_in[6];
    const float* b_mlp1 = (const float*)d_in[7];
    const float* w_mlp2 = (const float*)d_in[8];
    const float* b_mlp2 = (const float*)d_in[9];
    const float* w_ada  = (const float*)d_in[10];
    const float* b_ada  = (const float*)d_in[11];
    float* x = (float*)d_out;

    float  *mod;
    __half *xm, *qkv, *o, *h, *wq, *wo, *w1, *w2;
    cudaGetSymbolAddress((void**)&mod, g_mod);
    cudaGetSymbolAddress((void**)&xm,  g_xm);
    cudaGetSymbolAddress((void**)&qkv, g_qkv);
    cudaGetSymbolAddress((void**)&o,   g_o);
    cudaGetSymbolAddress((void**)&h,   g_h);
    cudaGetSymbolAddress((void**)&wq,  g_wqkv);
    cudaGetSymbolAddress((void**)&wo,  g_wout);
    cudaGetSymbolAddress((void**)&w1,  g_wmlp1);
    cudaGetSymbolAddress((void**)&w2,  g_wmlp2);

    const int gsmem = 3 * GSTG;   // 110592
    cudaFuncSetAttribute(gemm_fp16, cudaFuncAttributeMaxDynamicSharedMemorySize, gsmem);
    cudaFuncSetAttribute(attn_tc,   cudaFuncAttributeMaxDynamicSharedMemorySize, ASMEM);

    cudaMemcpyAsync(x, x_in, (size_t)M_ * D_ * sizeof(float), cudaMemcpyDeviceToDevice);

    {
        int n;
        n = L_*3*D_*D_/8;  cvt_kernel<<<(n+255)/256, 256>>>(w_qkv,  wq, n);
        n = L_*D_*D_/8;    cvt_kernel<<<(n+255)/256, 256>>>(w_out,  wo, n);
        n = L_*4*D_*D_/8;  cvt_kernel<<<(n+255)/256, 256>>>(w_mlp1, w1, n);
        n = L_*D_*4*D_/8;  cvt_kernel<<<(n+255)/256, 256>>>(w_mlp2, w2, n);
    }

    mod_kernel<<<(L_ * 6 * D_) / 8, 256>>>(c, w_ada, b_ada);

    for (int l = 0; l < L_; l++) {
        const float* modl = mod + (size_t)l * B_ * 6 * D_;
        // --- attention branch ---
        ln_mod_kernel<<<M_, 256>>>(x, modl, 0, D_, xm);
        gemm_fp16<<<dim3(3 * D_ / 128, M_ / 128), 128, gsmem>>>(
            xm, wq + (size_t)l * 3 * D_ * D_, b_qkv + (size_t)l * 3 * D_,
            nullptr, qkv, nullptr, nullptr, 0, 3 * D_, D_, 3);
        attn_tc<<<dim3(S_ / 128, B_ * H_), 256, ASMEM>>>(qkv, o);
        gemm_fp16<<<dim3(D_ / 128, M_ / 128), 128, gsmem>>>(
            o, wo + (size_t)l * D_ * D_, b_out + (size_t)l * D_,
            x, nullptr, x, modl, 2 * D_, D_, D_, 2);
        // --- MLP branch ---
        ln_mod_kernel<<<M_, 256>>>(x, modl, 3 * D_, 4 * D_, xm);
        gemm_fp16<<<dim3(4 * D_ / 128, M_ / 128), 128, gsmem>>>(
            xm, w1 + (size_t)l * 4 * D_ * D_, b_mlp1 + (size_t)l * 4 * D_,
            nullptr, h, nullptr, nullptr, 0, 4 * D_, D_, 1);
        gemm_fp16<<<dim3(D_ / 128, M_ / 128), 128, gsmem>>>(
            h, w2 + (size_t)l * D_ * 4 * D_, b_mlp2 + (size_t)l * D_,
            x, nullptr, x, modl, 5 * D_, D_, 4 * D_, 2);
    }
}